// round 14
// baseline (speedup 1.0000x reference)
#include <cuda_runtime.h>
#include <cuda_fp16.h>
#include <math.h>

#define NN 100000
#define EE 1600000
#define MM (EE + NN)
#define DD 128

struct __align__(8) Edge { int s; float w; };

// ---------------- scratch (static device allocations; no runtime alloc) ----
__device__ int   g_deg[NN];
__device__ float g_sumw[NN];
__device__ float g_loopw[NN];
__device__ int   g_rowptr[NN + 1];
__device__ int   g_wp[NN];
__device__ int   g_bsum[128];
__device__ Edge  g_edge[MM];
__device__ float g_as[NN];
__device__ float g_ad[NN];
__device__ __align__(16) __half2 g_Hh[(size_t)NN * 64];    // fp16 H
__device__ __align__(16) __half2 g_ACTh[(size_t)NN * 64];  // fp16 ACT
__device__ __align__(16) unsigned int g_Wfrag[2][8192];    // pre-fragmented fp16 W
__device__ float g_ce[2];

// ---------------- preprocessing ----------------
__global__ void k_init() {
    int i = blockIdx.x * blockDim.x + threadIdx.x;
    if (i < NN) { g_deg[i] = 0; g_sumw[i] = 0.f; }
}

// Pre-permute W (fp32 [L][128k][128n]) into per-(j,lane) paired fragment order:
// frag[kc*1024 + j*64 + lane*2 + i] = half2{ W[k][col], W[k+1][col] }
// k = kc*16 + tg*2 + i*8, col = j*8 + g, g=lane>>2, tg=lane&3.
__global__ void k_wfrag(const float* __restrict__ W) {
    int idx = blockIdx.x * blockDim.x + threadIdx.x;   // 16384 threads
    if (idx >= 16384) return;
    int layer = idx >> 13;
    int r = idx & 8191;
    int kc = r >> 10, j = (r >> 6) & 15;
    int rem = r & 63;
    int lane = rem >> 1, i = rem & 1;
    int g = lane >> 2, tg = lane & 3;
    int k = kc * 16 + tg * 2 + i * 8;
    int col = j * 8 + g;
    const float* Wl = W + layer * DD * DD;
    __half2 v = __floats2half2_rn(Wl[k * DD + col], Wl[(k + 1) * DD + col]);
    g_Wfrag[layer][r] = *(const unsigned int*)&v;
}

// edge_index is int32
__global__ void k_deg(const int* __restrict__ ei, const float* __restrict__ ew) {
    int i = blockIdx.x * blockDim.x + threadIdx.x;
    if (i < EE) {
        int d = ei[EE + i];
        atomicAdd(&g_deg[d], 1);
        atomicAdd(&g_sumw[d], ew[i]);
    }
}

__global__ void k_scan1() {
    __shared__ int s[1024];
    int i = blockIdx.x * 1024 + threadIdx.x;
    int v = (i < NN) ? g_deg[i] + 1 : 0;   // +1 self-loop
    s[threadIdx.x] = v;
    __syncthreads();
    for (int off = 1; off < 1024; off <<= 1) {
        int t = (threadIdx.x >= off) ? s[threadIdx.x - off] : 0;
        __syncthreads();
        s[threadIdx.x] += t;
        __syncthreads();
    }
    if (i < NN) g_rowptr[i] = s[threadIdx.x] - v;
    if (threadIdx.x == 1023) g_bsum[blockIdx.x] = s[1023];
}

// parallel block-sum scan (<=128 elems) + c_e = lew . att_edge
__global__ void k_scan2ce(int nb, const float* __restrict__ lew, const float* __restrict__ ae) {
    __shared__ int sc[128];
    int t = threadIdx.x;
    float p0 = lew[t] * ae[t];
    float p1 = lew[DD + t] * ae[DD + t];
    for (int o = 16; o; o >>= 1) {
        p0 += __shfl_xor_sync(0xffffffffu, p0, o);
        p1 += __shfl_xor_sync(0xffffffffu, p1, o);
    }
    __shared__ float s0[4], s1[4];
    if ((t & 31) == 0) { s0[t >> 5] = p0; s1[t >> 5] = p1; }

    int v = (t < nb) ? g_bsum[t] : 0;
    sc[t] = v;
    __syncthreads();
    for (int off = 1; off < 128; off <<= 1) {
        int a = (t >= off) ? sc[t - off] : 0;
        __syncthreads();
        sc[t] += a;
        __syncthreads();
    }
    if (t < nb) g_bsum[t] = sc[t] - v;
    if (t == 0) {
        g_ce[0] = s0[0] + s0[1] + s0[2] + s0[3];
        g_ce[1] = s1[0] + s1[1] + s1[2] + s1[3];
        g_rowptr[NN] = MM;
    }
}

__global__ void k_scan3() {
    int i = blockIdx.x * blockDim.x + threadIdx.x;
    if (i < NN) {
        int v = g_rowptr[i] + g_bsum[i >> 10];
        g_rowptr[i] = v;
        g_wp[i] = v;
        int d = g_deg[i];
        g_loopw[i] = g_sumw[i] / (float)(d > 1 ? d : 1);
    }
}

__global__ void k_scatter(const int* __restrict__ ei, const float* __restrict__ ew) {
    int i = blockIdx.x * blockDim.x + threadIdx.x;
    if (i < EE) {
        int s = ei[i];
        int d = ei[EE + i];
        int pos = atomicAdd(&g_wp[d], 1);
        Edge e; e.s = s; e.w = ew[i];
        g_edge[pos] = e;
    } else if (i < MM) {
        int n = i - EE;
        int pos = atomicAdd(&g_wp[n], 1);
        Edge e; e.s = n; e.w = g_loopw[n];
        g_edge[pos] = e;
    }
}

// ---------------- warp-autonomous tensor-core GEMM ----------------
// Each warp owns 16 rows: loads them to its private smem slice, __syncwarp,
// then m16n128 via 16x8 HMMA with B streamed from L2 (LDG.64).
// NO __syncthreads anywhere -> full SM-wide load/compute overlap.
template<int SRC>
__global__ void __launch_bounds__(256, 2)
k_gemm(const float* __restrict__ Xin, int layer,
       const float* __restrict__ asrc, const float* __restrict__ adst) {
    __shared__ __align__(16) __half sX[128][136];

    int tid = threadIdx.x;
    int warp = tid >> 5, lane = tid & 31;
    int g = lane >> 2, tg = lane & 3;
    int row0 = blockIdx.x * 128;
    int mrow = warp * 16;

    // ---- warp loads its own 16 rows ----
    if (SRC == 0) {
#pragma unroll
        for (int t = 0; t < 16; t++) {
            int r = mrow + t;
            float4 v = make_float4(0.f, 0.f, 0.f, 0.f);
            int gr = row0 + r;
            if (gr < NN) v = ((const float4*)Xin)[gr * 32 + lane];
            __half2 h0 = __floats2half2_rn(v.x, v.y);
            __half2 h1 = __floats2half2_rn(v.z, v.w);
            uint2 p = make_uint2(*(const unsigned int*)&h0, *(const unsigned int*)&h1);
            *(uint2*)&sX[r][lane * 4] = p;
        }
    } else {
#pragma unroll
        for (int t = 0; t < 8; t++) {
            int idx = t * 32 + lane;              // 256 uint4 slots for 16 rows
            int r = mrow + (idx >> 4);
            int c8 = idx & 15;
            uint4 v = make_uint4(0u, 0u, 0u, 0u);
            int gr = row0 + r;
            if (gr < NN) v = ((const uint4*)g_ACTh)[gr * 16 + c8];
            *(uint4*)&sX[r][c8 * 8] = v;
        }
    }
    __syncwarp();

    float c[16][4];
#pragma unroll
    for (int j = 0; j < 16; j++)
#pragma unroll
        for (int q = 0; q < 4; q++) c[j][q] = 0.f;

    const uint2* wf = (const uint2*)&g_Wfrag[layer][0];   // [kc][j][lane] pairs

#pragma unroll
    for (int kc = 0; kc < 8; kc++) {
        int k0 = kc * 16;
        unsigned int a0 = *(const unsigned int*)&sX[mrow + g][k0 + tg * 2];
        unsigned int a1 = *(const unsigned int*)&sX[mrow + g + 8][k0 + tg * 2];
        unsigned int a2 = *(const unsigned int*)&sX[mrow + g][k0 + tg * 2 + 8];
        unsigned int a3 = *(const unsigned int*)&sX[mrow + g + 8][k0 + tg * 2 + 8];
#pragma unroll
        for (int j = 0; j < 16; j++) {
            uint2 bb = __ldg(&wf[kc * 512 + j * 32 + lane]);
            asm volatile(
                "mma.sync.aligned.m16n8k16.row.col.f32.f16.f16.f32 "
                "{%0,%1,%2,%3}, {%4,%5,%6,%7}, {%8,%9}, {%0,%1,%2,%3};\n"
                : "+f"(c[j][0]), "+f"(c[j][1]), "+f"(c[j][2]), "+f"(c[j][3])
                : "r"(a0), "r"(a1), "r"(a2), "r"(a3), "r"(bb.x), "r"(bb.y));
        }
    }

    // ---- epilogue: fp16 H store + fused alpha (fp32, alpha vecs via L2) ----
    int r0 = row0 + mrow + g;
    int r1 = r0 + 8;
    bool ok0 = (r0 < NN), ok1 = (r1 < NN);
    float ps0 = 0.f, pd0 = 0.f, ps1 = 0.f, pd1 = 0.f;
#pragma unroll
    for (int j = 0; j < 16; j++) {
        int c0i = j * 8 + tg * 2;
        float av0 = __ldg(asrc + c0i), av1 = __ldg(asrc + c0i + 1);
        float bv0 = __ldg(adst + c0i), bv1 = __ldg(adst + c0i + 1);
        ps0 += c[j][0] * av0 + c[j][1] * av1;
        pd0 += c[j][0] * bv0 + c[j][1] * bv1;
        ps1 += c[j][2] * av0 + c[j][3] * av1;
        pd1 += c[j][2] * bv0 + c[j][3] * bv1;
        if (ok0) g_Hh[(size_t)r0 * 64 + (c0i >> 1)] = __floats2half2_rn(c[j][0], c[j][1]);
        if (ok1) g_Hh[(size_t)r1 * 64 + (c0i >> 1)] = __floats2half2_rn(c[j][2], c[j][3]);
    }
#pragma unroll
    for (int o = 1; o <= 2; o <<= 1) {
        ps0 += __shfl_xor_sync(0xffffffffu, ps0, o);
        pd0 += __shfl_xor_sync(0xffffffffu, pd0, o);
        ps1 += __shfl_xor_sync(0xffffffffu, ps1, o);
        pd1 += __shfl_xor_sync(0xffffffffu, pd1, o);
    }
    if (tg == 0) {
        if (ok0) { g_as[r0] = ps0; g_ad[r0] = pd0; }
        if (ok1) { g_as[r1] = ps1; g_ad[r1] = pd1; }
    }
}

__device__ __forceinline__ float leaky(float v) { return v > 0.f ? v : 0.2f * v; }
__device__ __forceinline__ float gelu(float v) {
    return 0.5f * v * (1.f + erff(v * 0.70710678118f));
}

__device__ __forceinline__ void fma_row(float4& acc, float p, uint2 h) {
    float2 f0 = __half22float2(*(const __half2*)&h.x);
    float2 f1 = __half22float2(*(const __half2*)&h.y);
    acc.x = fmaf(p, f0.x, acc.x);
    acc.y = fmaf(p, f0.y, acc.y);
    acc.z = fmaf(p, f1.x, acc.z);
    acc.w = fmaf(p, f1.y, acc.w);
}

// ---------------- single-pass online-softmax aggregation: warp per node -----
// 4 accumulator chains, 4 loads in flight; scalar remainder.
template<int FUSE_LN>
__global__ void k_agg(int layer, const float* __restrict__ biasl,
                      const float* __restrict__ x, const float* __restrict__ gam,
                      const float* __restrict__ bet, float* __restrict__ outp) {
    int gg = blockIdx.x * blockDim.x + threadIdx.x;
    int n = gg >> 5, lane = gg & 31;
    if (n >= NN) return;
    int beg = g_rowptr[n], end = g_rowptr[n + 1];
    float ad = g_ad[n];
    float ce = g_ce[layer];

    float m = -3.0e38f, z = 0.f;
    float4 accA = make_float4(0.f, 0.f, 0.f, 0.f);
    float4 accB = make_float4(0.f, 0.f, 0.f, 0.f);
    float4 accC = make_float4(0.f, 0.f, 0.f, 0.f);
    float4 accD = make_float4(0.f, 0.f, 0.f, 0.f);
    const uint2* Hv = (const uint2*)g_Hh;   // row = 32 uint2, lane owns one

    for (int base = beg; base < end; base += 32) {
        int j = base + lane;
        float l = -3.0e38f; int s = 0;
        if (j < end) {
            Edge e = g_edge[j];
            s = e.s;
            l = leaky(g_as[s] + ad + ce * e.w);
        }
        float bm = l;
#pragma unroll
        for (int o = 16; o; o >>= 1) bm = fmaxf(bm, __shfl_xor_sync(0xffffffffu, bm, o));
        float mn = fmaxf(m, bm);
        float scale = __expf(m - mn);
        z *= scale;
        accA.x *= scale; accA.y *= scale; accA.z *= scale; accA.w *= scale;
        accB.x *= scale; accB.y *= scale; accB.z *= scale; accB.w *= scale;
        accC.x *= scale; accC.y *= scale; accC.z *= scale; accC.w *= scale;
        accD.x *= scale; accD.y *= scale; accD.z *= scale; accD.w *= scale;
        m = mn;
        float p = (j < end) ? __expf(l - m) : 0.f;
        z += p;

        int cnt = min(32, end - base);
        int t = 0;
        for (; t + 3 < cnt; t += 4) {
            float pa = __shfl_sync(0xffffffffu, p, t);
            float pb = __shfl_sync(0xffffffffu, p, t + 1);
            float pc = __shfl_sync(0xffffffffu, p, t + 2);
            float pd = __shfl_sync(0xffffffffu, p, t + 3);
            int sa = __shfl_sync(0xffffffffu, s, t);
            int sb = __shfl_sync(0xffffffffu, s, t + 1);
            int sc = __shfl_sync(0xffffffffu, s, t + 2);
            int sd = __shfl_sync(0xffffffffu, s, t + 3);
            uint2 ha = Hv[(size_t)sa * 32 + lane];
            uint2 hb = Hv[(size_t)sb * 32 + lane];
            uint2 hc = Hv[(size_t)sc * 32 + lane];
            uint2 hd = Hv[(size_t)sd * 32 + lane];
            fma_row(accA, pa, ha);
            fma_row(accB, pb, hb);
            fma_row(accC, pc, hc);
            fma_row(accD, pd, hd);
        }
        for (; t < cnt; t++) {
            float pa = __shfl_sync(0xffffffffu, p, t);
            int   sa = __shfl_sync(0xffffffffu, s, t);
            uint2 ha = Hv[(size_t)sa * 32 + lane];
            fma_row(accA, pa, ha);
        }
    }
#pragma unroll
    for (int o = 16; o; o >>= 1) z += __shfl_xor_sync(0xffffffffu, z, o);
    float inv = 1.f / z;
    float4 b = ((const float4*)biasl)[lane];
    float4 o;
    o.x = gelu(((accA.x + accB.x) + (accC.x + accD.x)) * inv + b.x);
    o.y = gelu(((accA.y + accB.y) + (accC.y + accD.y)) * inv + b.y);
    o.z = gelu(((accA.z + accB.z) + (accC.z + accD.z)) * inv + b.z);
    o.w = gelu(((accA.w + accB.w) + (accC.w + accD.w)) * inv + b.w);

    if (FUSE_LN == 0) {
        __half2 h0 = __floats2half2_rn(o.x, o.y);
        __half2 h1 = __floats2half2_rn(o.z, o.w);
        uint2 p = make_uint2(*(const unsigned int*)&h0, *(const unsigned int*)&h1);
        ((uint2*)g_ACTh)[(size_t)n * 32 + lane] = p;
    } else {
        float4 v = ((const float4*)x)[n * 32 + lane];
        v.x += o.x; v.y += o.y; v.z += o.z; v.w += o.w;
        float s = v.x + v.y + v.z + v.w;
#pragma unroll
        for (int oo = 16; oo; oo >>= 1) s += __shfl_xor_sync(0xffffffffu, s, oo);
        float mu = s * (1.f / 128.f);
        float dx = v.x - mu, dy = v.y - mu, dz = v.z - mu, dw = v.w - mu;
        float q = dx * dx + dy * dy + dz * dz + dw * dw;
#pragma unroll
        for (int oo = 16; oo; oo >>= 1) q += __shfl_xor_sync(0xffffffffu, q, oo);
        float r = rsqrtf(q * (1.f / 128.f) + 1e-5f);
        float4 gg2 = ((const float4*)gam)[lane];
        float4 bb = ((const float4*)bet)[lane];
        float4 o4;
        o4.x = dx * r * gg2.x + bb.x;
        o4.y = dy * r * gg2.y + bb.y;
        o4.z = dz * r * gg2.z + bb.z;
        o4.w = dw * r * gg2.w + bb.w;
        ((float4*)outp)[n * 32 + lane] = o4;
    }
}

// ---------------- host: kernel launches ONLY ----------------
extern "C" void kernel_launch(void* const* d_in, const int* in_sizes, int n_in,
                              void* d_out, int out_size) {
    const float* x     = (const float*)d_in[0];
    const int*   ei    = (const int*)d_in[1];     // int32
    const float* ew    = (const float*)d_in[2];
    const float* W     = (const float*)d_in[3];
    const float* asrc  = (const float*)d_in[4];
    const float* adst  = (const float*)d_in[5];
    const float* lew   = (const float*)d_in[6];
    const float* aedge = (const float*)d_in[7];
    const float* bias  = (const float*)d_in[8];
    const float* gam   = (const float*)d_in[9];
    const float* bet   = (const float*)d_in[10];
    float* out = (float*)d_out;
    (void)in_sizes; (void)n_in; (void)out_size;

    const int TB = 256;
    const int gN  = (NN + TB - 1) / TB;
    const int gE  = (EE + TB - 1) / TB;
    const int gM  = (MM + TB - 1) / TB;
    const int gW  = (NN * 32 + TB - 1) / TB;      // one warp per node
    const int nScanBlk = (NN + 1023) / 1024;       // 98
    const int gGemm = (NN + 127) / 128;            // 782

    // launch order places k_gemm<0> at index 3 (ncu capture slot)
    k_init<<<gN, TB>>>();                               // 0
    k_wfrag<<<64, TB>>>(W);                             // 1
    k_deg<<<gE, TB>>>(ei, ew);                          // 2
    k_gemm<0><<<gGemm, TB>>>(x, 0, asrc, adst);         // 3  <- profiled
    k_scan1<<<nScanBlk, 1024>>>();                      // 4
    k_scan2ce<<<1, 128>>>(nScanBlk, lew, aedge);        // 5
    k_scan3<<<gN, TB>>>();                              // 6
    k_scatter<<<gM, TB>>>(ei, ew);                      // 7
    k_agg<0><<<gW, TB>>>(0, bias, nullptr, nullptr, nullptr, nullptr);   // 8
    k_gemm<1><<<gGemm, TB>>>(nullptr, 1, asrc + DD, adst + DD);          // 9
    k_agg<1><<<gW, TB>>>(1, bias + DD, x, gam, bet, out);                // 10
}

// round 15
// speedup vs baseline: 1.1131x; 1.1131x over previous
#include <cuda_runtime.h>
#include <cuda_fp16.h>
#include <math.h>

#define NN 100000
#define EE 1600000
#define MM (EE + NN)
#define DD 128

struct __align__(8) Edge { int s; float w; };

// ---------------- scratch (static device allocations; no runtime alloc) ----
__device__ int   g_deg[NN];
__device__ float g_sumw[NN];
__device__ float g_loopw[NN];
__device__ int   g_rowptr[NN + 1];
__device__ int   g_wp[NN];
__device__ int   g_bsum[128];
__device__ Edge  g_edge[MM];
__device__ float g_as[NN];
__device__ float g_ad[NN];
__device__ __align__(16) __half2 g_Hh[(size_t)NN * 64];    // fp16 H
__device__ __align__(16) __half2 g_ACTh[(size_t)NN * 64];  // fp16 ACT
__device__ __align__(16) unsigned int g_Wfrag[2][8192];    // pre-fragmented fp16 W
__device__ float g_ce[2];

// ---------------- preprocessing ----------------
__global__ void k_init() {
    int i = blockIdx.x * blockDim.x + threadIdx.x;
    if (i < NN) { g_deg[i] = 0; g_sumw[i] = 0.f; }
}

// Pre-permute W (fp32 [L][128k][128n]) into per-(j,lane) paired fragment order:
// frag[kc*1024 + j*64 + lane*2 + i] = half2{ W[k][col], W[k+1][col] }
// k = kc*16 + tg*2 + i*8, col = j*8 + g, g=lane>>2, tg=lane&3.
__global__ void k_wfrag(const float* __restrict__ W) {
    int idx = blockIdx.x * blockDim.x + threadIdx.x;   // 16384 threads
    if (idx >= 16384) return;
    int layer = idx >> 13;
    int r = idx & 8191;
    int kc = r >> 10, j = (r >> 6) & 15;
    int rem = r & 63;
    int lane = rem >> 1, i = rem & 1;
    int g = lane >> 2, tg = lane & 3;
    int k = kc * 16 + tg * 2 + i * 8;
    int col = j * 8 + g;
    const float* Wl = W + layer * DD * DD;
    __half2 v = __floats2half2_rn(Wl[k * DD + col], Wl[(k + 1) * DD + col]);
    g_Wfrag[layer][r] = *(const unsigned int*)&v;
}

// edge_index is int32
__global__ void k_deg(const int* __restrict__ ei, const float* __restrict__ ew) {
    int i = blockIdx.x * blockDim.x + threadIdx.x;
    if (i < EE) {
        int d = ei[EE + i];
        atomicAdd(&g_deg[d], 1);
        atomicAdd(&g_sumw[d], ew[i]);
    }
}

__global__ void k_scan1() {
    __shared__ int s[1024];
    int i = blockIdx.x * 1024 + threadIdx.x;
    int v = (i < NN) ? g_deg[i] + 1 : 0;   // +1 self-loop
    s[threadIdx.x] = v;
    __syncthreads();
    for (int off = 1; off < 1024; off <<= 1) {
        int t = (threadIdx.x >= off) ? s[threadIdx.x - off] : 0;
        __syncthreads();
        s[threadIdx.x] += t;
        __syncthreads();
    }
    if (i < NN) g_rowptr[i] = s[threadIdx.x] - v;
    if (threadIdx.x == 1023) g_bsum[blockIdx.x] = s[1023];
}

// parallel block-sum scan (<=128 elems) + c_e = lew . att_edge
__global__ void k_scan2ce(int nb, const float* __restrict__ lew, const float* __restrict__ ae) {
    __shared__ int sc[128];
    int t = threadIdx.x;
    float p0 = lew[t] * ae[t];
    float p1 = lew[DD + t] * ae[DD + t];
    for (int o = 16; o; o >>= 1) {
        p0 += __shfl_xor_sync(0xffffffffu, p0, o);
        p1 += __shfl_xor_sync(0xffffffffu, p1, o);
    }
    __shared__ float s0[4], s1[4];
    if ((t & 31) == 0) { s0[t >> 5] = p0; s1[t >> 5] = p1; }

    int v = (t < nb) ? g_bsum[t] : 0;
    sc[t] = v;
    __syncthreads();
    for (int off = 1; off < 128; off <<= 1) {
        int a = (t >= off) ? sc[t - off] : 0;
        __syncthreads();
        sc[t] += a;
        __syncthreads();
    }
    if (t < nb) g_bsum[t] = sc[t] - v;
    if (t == 0) {
        g_ce[0] = s0[0] + s0[1] + s0[2] + s0[3];
        g_ce[1] = s1[0] + s1[1] + s1[2] + s1[3];
        g_rowptr[NN] = MM;
    }
}

__global__ void k_scan3() {
    int i = blockIdx.x * blockDim.x + threadIdx.x;
    if (i < NN) {
        int v = g_rowptr[i] + g_bsum[i >> 10];
        g_rowptr[i] = v;
        g_wp[i] = v;
        int d = g_deg[i];
        g_loopw[i] = g_sumw[i] / (float)(d > 1 ? d : 1);
    }
}

__global__ void k_scatter(const int* __restrict__ ei, const float* __restrict__ ew) {
    int i = blockIdx.x * blockDim.x + threadIdx.x;
    if (i < EE) {
        int s = ei[i];
        int d = ei[EE + i];
        int pos = atomicAdd(&g_wp[d], 1);
        Edge e; e.s = s; e.w = ew[i];
        g_edge[pos] = e;
    } else if (i < MM) {
        int n = i - EE;
        int pos = atomicAdd(&g_wp[n], 1);
        Edge e; e.s = n; e.w = g_loopw[n];
        g_edge[pos] = e;
    }
}

// ---------------- warp-autonomous tensor-core GEMM (R14-proven) ----------
template<int SRC>
__global__ void __launch_bounds__(256, 2)
k_gemm(const float* __restrict__ Xin, int layer,
       const float* __restrict__ asrc, const float* __restrict__ adst) {
    __shared__ __align__(16) __half sX[128][136];

    int tid = threadIdx.x;
    int warp = tid >> 5, lane = tid & 31;
    int g = lane >> 2, tg = lane & 3;
    int row0 = blockIdx.x * 128;
    int mrow = warp * 16;

    // ---- warp loads its own 16 rows ----
    if (SRC == 0) {
#pragma unroll
        for (int t = 0; t < 16; t++) {
            int r = mrow + t;
            float4 v = make_float4(0.f, 0.f, 0.f, 0.f);
            int gr = row0 + r;
            if (gr < NN) v = ((const float4*)Xin)[gr * 32 + lane];
            __half2 h0 = __floats2half2_rn(v.x, v.y);
            __half2 h1 = __floats2half2_rn(v.z, v.w);
            uint2 p = make_uint2(*(const unsigned int*)&h0, *(const unsigned int*)&h1);
            *(uint2*)&sX[r][lane * 4] = p;
        }
    } else {
#pragma unroll
        for (int t = 0; t < 8; t++) {
            int idx = t * 32 + lane;              // 256 uint4 slots for 16 rows
            int r = mrow + (idx >> 4);
            int c8 = idx & 15;
            uint4 v = make_uint4(0u, 0u, 0u, 0u);
            int gr = row0 + r;
            if (gr < NN) v = ((const uint4*)g_ACTh)[gr * 16 + c8];
            *(uint4*)&sX[r][c8 * 8] = v;
        }
    }
    __syncwarp();

    float c[16][4];
#pragma unroll
    for (int j = 0; j < 16; j++)
#pragma unroll
        for (int q = 0; q < 4; q++) c[j][q] = 0.f;

    const uint2* wf = (const uint2*)&g_Wfrag[layer][0];   // [kc][j][lane] pairs

#pragma unroll
    for (int kc = 0; kc < 8; kc++) {
        int k0 = kc * 16;
        unsigned int a0 = *(const unsigned int*)&sX[mrow + g][k0 + tg * 2];
        unsigned int a1 = *(const unsigned int*)&sX[mrow + g + 8][k0 + tg * 2];
        unsigned int a2 = *(const unsigned int*)&sX[mrow + g][k0 + tg * 2 + 8];
        unsigned int a3 = *(const unsigned int*)&sX[mrow + g + 8][k0 + tg * 2 + 8];
#pragma unroll
        for (int j = 0; j < 16; j++) {
            uint2 bb = __ldg(&wf[kc * 512 + j * 32 + lane]);
            asm volatile(
                "mma.sync.aligned.m16n8k16.row.col.f32.f16.f16.f32 "
                "{%0,%1,%2,%3}, {%4,%5,%6,%7}, {%8,%9}, {%0,%1,%2,%3};\n"
                : "+f"(c[j][0]), "+f"(c[j][1]), "+f"(c[j][2]), "+f"(c[j][3])
                : "r"(a0), "r"(a1), "r"(a2), "r"(a3), "r"(bb.x), "r"(bb.y));
        }
    }

    // ---- epilogue: fp16 H store + fused alpha (fp32, alpha vecs via L2) ----
    int r0 = row0 + mrow + g;
    int r1 = r0 + 8;
    bool ok0 = (r0 < NN), ok1 = (r1 < NN);
    float ps0 = 0.f, pd0 = 0.f, ps1 = 0.f, pd1 = 0.f;
#pragma unroll
    for (int j = 0; j < 16; j++) {
        int c0i = j * 8 + tg * 2;
        float av0 = __ldg(asrc + c0i), av1 = __ldg(asrc + c0i + 1);
        float bv0 = __ldg(adst + c0i), bv1 = __ldg(adst + c0i + 1);
        ps0 += c[j][0] * av0 + c[j][1] * av1;
        pd0 += c[j][0] * bv0 + c[j][1] * bv1;
        ps1 += c[j][2] * av0 + c[j][3] * av1;
        pd1 += c[j][2] * bv0 + c[j][3] * bv1;
        if (ok0) g_Hh[(size_t)r0 * 64 + (c0i >> 1)] = __floats2half2_rn(c[j][0], c[j][1]);
        if (ok1) g_Hh[(size_t)r1 * 64 + (c0i >> 1)] = __floats2half2_rn(c[j][2], c[j][3]);
    }
#pragma unroll
    for (int o = 1; o <= 2; o <<= 1) {
        ps0 += __shfl_xor_sync(0xffffffffu, ps0, o);
        pd0 += __shfl_xor_sync(0xffffffffu, pd0, o);
        ps1 += __shfl_xor_sync(0xffffffffu, ps1, o);
        pd1 += __shfl_xor_sync(0xffffffffu, pd1, o);
    }
    if (tg == 0) {
        if (ok0) { g_as[r0] = ps0; g_ad[r0] = pd0; }
        if (ok1) { g_as[r1] = ps1; g_ad[r1] = pd1; }
    }
}

__device__ __forceinline__ float leaky(float v) { return v > 0.f ? v : 0.2f * v; }
__device__ __forceinline__ float gelu(float v) {
    return 0.5f * v * (1.f + erff(v * 0.70710678118f));
}

__device__ __forceinline__ void fma8(float* acc, float p, uint4 h) {
    float2 f0 = __half22float2(*(const __half2*)&h.x);
    float2 f1 = __half22float2(*(const __half2*)&h.y);
    float2 f2 = __half22float2(*(const __half2*)&h.z);
    float2 f3 = __half22float2(*(const __half2*)&h.w);
    acc[0] = fmaf(p, f0.x, acc[0]); acc[1] = fmaf(p, f0.y, acc[1]);
    acc[2] = fmaf(p, f1.x, acc[2]); acc[3] = fmaf(p, f1.y, acc[3]);
    acc[4] = fmaf(p, f2.x, acc[4]); acc[5] = fmaf(p, f2.y, acc[5]);
    acc[6] = fmaf(p, f3.x, acc[6]); acc[7] = fmaf(p, f3.y, acc[7]);
}

// ---------------- half-warp online-softmax aggregation: 2 nodes / warp -----
// 16-lane group owns one node; lane hl loads 16B of the 256B gathered row.
// All shuffles use disjoint half-masks (legal under half-warp divergence).
template<int FUSE_LN>
__global__ void k_agg(int layer, const float* __restrict__ biasl,
                      const float* __restrict__ x, const float* __restrict__ gam,
                      const float* __restrict__ bet, float* __restrict__ outp) {
    int gg = blockIdx.x * blockDim.x + threadIdx.x;
    int warpid = gg >> 5, lane = gg & 31;
    int hw = lane >> 4, hl = lane & 15;
    int n = warpid * 2 + hw;
    if (n >= NN) return;
    unsigned HM = hw ? 0xFFFF0000u : 0x0000FFFFu;
    int sl0 = hw << 4;   // first absolute lane of this half

    int beg = g_rowptr[n], end = g_rowptr[n + 1];
    float ad = g_ad[n];
    float ce = g_ce[layer];

    float m = -3.0e38f, z = 0.f;
    float accA[8], accB[8];
#pragma unroll
    for (int k = 0; k < 8; k++) { accA[k] = 0.f; accB[k] = 0.f; }
    const uint4* Hv = (const uint4*)g_Hh;   // row = 16 uint4, lane hl owns one

    for (int base = beg; base < end; base += 16) {
        int j = base + hl;
        float l = -3.0e38f; int s = 0;
        if (j < end) {
            Edge e = g_edge[j];
            s = e.s;
            l = leaky(g_as[s] + ad + ce * e.w);
        }
        float bm = l;
#pragma unroll
        for (int o = 8; o; o >>= 1) bm = fmaxf(bm, __shfl_xor_sync(HM, bm, o));
        float mn = fmaxf(m, bm);
        float scale = __expf(m - mn);
        z *= scale;
#pragma unroll
        for (int k = 0; k < 8; k++) { accA[k] *= scale; accB[k] *= scale; }
        m = mn;
        float p = (j < end) ? __expf(l - m) : 0.f;
        z += p;

        int cnt = min(16, end - base);
        int t = 0;
        for (; t + 1 < cnt; t += 2) {
            float pa = __shfl_sync(HM, p, sl0 + t);
            float pb = __shfl_sync(HM, p, sl0 + t + 1);
            int   sa = __shfl_sync(HM, s, sl0 + t);
            int   sb = __shfl_sync(HM, s, sl0 + t + 1);
            uint4 ha = Hv[(size_t)sa * 16 + hl];
            uint4 hb = Hv[(size_t)sb * 16 + hl];
            fma8(accA, pa, ha);
            fma8(accB, pb, hb);
        }
        if (t < cnt) {
            float pa = __shfl_sync(HM, p, sl0 + t);
            int   sa = __shfl_sync(HM, s, sl0 + t);
            uint4 ha = Hv[(size_t)sa * 16 + hl];
            fma8(accA, pa, ha);
        }
    }
#pragma unroll
    for (int o = 8; o; o >>= 1) z += __shfl_xor_sync(HM, z, o);
    float inv = 1.f / z;

    float4 b0 = ((const float4*)biasl)[hl * 2];
    float4 b1 = ((const float4*)biasl)[hl * 2 + 1];
    float bb8[8] = {b0.x, b0.y, b0.z, b0.w, b1.x, b1.y, b1.z, b1.w};
    float o8[8];
#pragma unroll
    for (int k = 0; k < 8; k++)
        o8[k] = gelu((accA[k] + accB[k]) * inv + bb8[k]);

    if (FUSE_LN == 0) {
        __half2 h0 = __floats2half2_rn(o8[0], o8[1]);
        __half2 h1 = __floats2half2_rn(o8[2], o8[3]);
        __half2 h2 = __floats2half2_rn(o8[4], o8[5]);
        __half2 h3 = __floats2half2_rn(o8[6], o8[7]);
        uint4 pk = make_uint4(*(const unsigned int*)&h0, *(const unsigned int*)&h1,
                              *(const unsigned int*)&h2, *(const unsigned int*)&h3);
        ((uint4*)g_ACTh)[(size_t)n * 16 + hl] = pk;
    } else {
        float4 x0 = ((const float4*)x)[n * 32 + hl * 2];
        float4 x1 = ((const float4*)x)[n * 32 + hl * 2 + 1];
        float v8[8] = {x0.x + o8[0], x0.y + o8[1], x0.z + o8[2], x0.w + o8[3],
                       x1.x + o8[4], x1.y + o8[5], x1.z + o8[6], x1.w + o8[7]};
        float s = 0.f;
#pragma unroll
        for (int k = 0; k < 8; k++) s += v8[k];
#pragma unroll
        for (int o = 8; o; o >>= 1) s += __shfl_xor_sync(HM, s, o);
        float mu = s * (1.f / 128.f);
        float q = 0.f;
#pragma unroll
        for (int k = 0; k < 8; k++) { v8[k] -= mu; q += v8[k] * v8[k]; }
#pragma unroll
        for (int o = 8; o; o >>= 1) q += __shfl_xor_sync(HM, q, o);
        float r = rsqrtf(q * (1.f / 128.f) + 1e-5f);
        float4 g0 = ((const float4*)gam)[hl * 2];
        float4 g1 = ((const float4*)gam)[hl * 2 + 1];
        float4 be0 = ((const float4*)bet)[hl * 2];
        float4 be1 = ((const float4*)bet)[hl * 2 + 1];
        float4 y0, y1;
        y0.x = v8[0] * r * g0.x + be0.x;
        y0.y = v8[1] * r * g0.y + be0.y;
        y0.z = v8[2] * r * g0.z + be0.z;
        y0.w = v8[3] * r * g0.w + be0.w;
        y1.x = v8[4] * r * g1.x + be1.x;
        y1.y = v8[5] * r * g1.y + be1.y;
        y1.z = v8[6] * r * g1.z + be1.z;
        y1.w = v8[7] * r * g1.w + be1.w;
        ((float4*)outp)[n * 32 + hl * 2] = y0;
        ((float4*)outp)[n * 32 + hl * 2 + 1] = y1;
    }
}

// ---------------- host: kernel launches ONLY ----------------
extern "C" void kernel_launch(void* const* d_in, const int* in_sizes, int n_in,
                              void* d_out, int out_size) {
    const float* x     = (const float*)d_in[0];
    const int*   ei    = (const int*)d_in[1];     // int32
    const float* ew    = (const float*)d_in[2];
    const float* W     = (const float*)d_in[3];
    const float* asrc  = (const float*)d_in[4];
    const float* adst  = (const float*)d_in[5];
    const float* lew   = (const float*)d_in[6];
    const float* aedge = (const float*)d_in[7];
    const float* bias  = (const float*)d_in[8];
    const float* gam   = (const float*)d_in[9];
    const float* bet   = (const float*)d_in[10];
    float* out = (float*)d_out;
    (void)in_sizes; (void)n_in; (void)out_size;

    const int TB = 256;
    const int gN  = (NN + TB - 1) / TB;
    const int gE  = (EE + TB - 1) / TB;
    const int gM  = (MM + TB - 1) / TB;
    const int gW2 = ((NN + 1) / 2 * 32 + TB - 1) / TB;   // 2 nodes per warp
    const int nScanBlk = (NN + 1023) / 1024;       // 98
    const int gGemm = (NN + 127) / 128;            // 782

    // launch order places k_gemm<0> at index 3 (ncu capture slot)
    k_init<<<gN, TB>>>();                               // 0
    k_wfrag<<<64, TB>>>(W);                             // 1
    k_deg<<<gE, TB>>>(ei, ew);                          // 2
    k_gemm<0><<<gGemm, TB>>>(x, 0, asrc, adst);         // 3  <- profiled
    k_scan1<<<nScanBlk, 1024>>>();                      // 4
    k_scan2ce<<<1, 128>>>(nScanBlk, lew, aedge);        // 5
    k_scan3<<<gN, TB>>>();                              // 6
    k_scatter<<<gM, TB>>>(ei, ew);                      // 7
    k_agg<0><<<gW2, TB>>>(0, bias, nullptr, nullptr, nullptr, nullptr);  // 8
    k_gemm<1><<<gGemm, TB>>>(nullptr, 1, asrc + DD, adst + DD);          // 9
    k_agg<1><<<gW2, TB>>>(1, bias + DD, x, gam, bet, out);               // 10
}